// round 9
// baseline (speedup 1.0000x reference)
#include <cuda_runtime.h>
#include <cstdint>

// S4D Vandermonde kernel:  K[h,l] = 2 * sum_n C_eff[h,n] * exp(dtA[h,n] * l)
// H=256, NH=N/2=32, L=16384.
//
// With this problem's init dtA[h,n] is constant across n, so
// K[h,l] = S[h] * exp(dtA[h]*l): one geometric recurrence per head.
// R9: block-level setup. Warp 0 alone runs the LDG -> coeff -> ballot ->
// shfl-reduce prologue and publishes {S, E, q1, stp, flag} (+ per-n c/dtA
// for the cold path) through shared memory; the other 7 warps wait at one
// barrier and read 4 broadcast LDS values. This cuts param LDG traffic and
// front-batched-load L1tex queue pressure 8x vs the per-warp prologue (R8),
// which the R5-R8 sweep showed to be the remaining latency-exposed term.
// Hot loop unchanged from R8: seed = S*exp(E*lb), then STG.128 + 2 mul.f32x2
// per j-step. Uniformity of dtA across n verified at runtime (warp ballot),
// cold fallback evaluates directly from smem coefficients.

#define TPB    256
#define NH     32
#define WPB    (TPB / 32)      // warps per block
#define JF     4               // float4 stores per lane
#define WCHUNK (32 * 4 * JF)   // 512 l-elements per warp
#define LOG2E  1.4426950408889634f

typedef unsigned long long ull;

__device__ __forceinline__ float ex2(float x) {
    float y; asm("ex2.approx.f32 %0, %1;" : "=f"(y) : "f"(x));
    return y;
}
__device__ __forceinline__ ull mul2(ull a, ull b) {
    ull d; asm("mul.rn.f32x2 %0, %1, %2;" : "=l"(d) : "l"(a), "l"(b));
    return d;
}
__device__ __forceinline__ ull pack2(float lo, float hi) {
    ull u; asm("mov.b64 %0, {%1, %2};" : "=l"(u) : "f"(lo), "f"(hi));
    return u;
}
__device__ __forceinline__ void unpack2(ull u, float& lo, float& hi) {
    asm("mov.b64 {%0, %1}, %2;" : "=f"(lo), "=f"(hi) : "l"(u));
}

__global__ void __launch_bounds__(TPB) s4d_kernel(
    const float* __restrict__ log_dt,      // [H]
    const float* __restrict__ C,           // [H, NH]
    const float* __restrict__ log_A_real,  // [H, NH]
    const float* __restrict__ A_imag,      // [H, NH]
    float* __restrict__ out,               // [H, L]
    int L)
{
    __shared__ float s_c[NH];              // cold path
    __shared__ float s_dtA[NH];            // cold path
    __shared__ float s_S, s_E, s_q1, s_stp;
    __shared__ int   s_flag;

    const int h    = blockIdx.y;
    const int t    = threadIdx.x;
    const int lane = t & 31;

    if (t < 32) {   // setup warp: lane == n. Mirrors reference fp32 math with
                    // MUFU-grade exp/div (rel err ~2^-21 vs the 1e-3 gate).
        float dt     = ex2(log_dt[h] * LOG2E);
        float Ar     = -ex2(log_A_real[h * NH + lane] * LOG2E);
        float Ai     = A_imag[h * NH + lane];
        float dtA    = Ar * dt;
        float den    = Ar * Ar + Ai * Ai;
        float expdtA = ex2(dtA * LOG2E);
        float c = __fdividef(2.0f * C[h * NH + lane] * (expdtA - 1.0f) * Ar, den);

        s_c[lane]   = c;
        s_dtA[lane] = dtA;

        const float dtA0  = __shfl_sync(0xffffffffu, dtA, 0);
        const unsigned eq = __ballot_sync(0xffffffffu,
                              __float_as_uint(dtA) == __float_as_uint(dtA0));
        float S = c;
#pragma unroll
        for (int o = 16; o; o >>= 1)
            S += __shfl_xor_sync(0xffffffffu, S, o);

        if (lane == 0) {
            float E = dtA0 * LOG2E;
            s_S    = S;
            s_E    = E;
            s_q1   = expdtA;              // lane0's exp(dtA) == exp(dtA0)
            s_stp  = ex2(E * 128.0f);     // j-step ratio (32 lanes * 4)
            s_flag = (eq == 0xffffffffu);
        }
    }
    __syncthreads();

    const int cbase = (blockIdx.x * WPB + (t >> 5)) * WCHUNK;
    if (cbase >= L) return;
    float* obase = out + (size_t)h * L + cbase;

    if (s_flag) {
        // ---- hot path: K = S * exp(dtA0 * l); S folded into the seed ----
        const float S   = s_S;
        const float E   = s_E;
        const float q1  = s_q1;
        const float stp = s_stp;

        float p0 = S * ex2(E * (float)(cbase + 4 * lane));   // one MUFU/thread
        float p1 = p0 * q1;
        float p2 = p1 * q1;
        float p3 = p2 * q1;

        ull pa = pack2(p0, p1);
        ull pb = pack2(p2, p3);
        const ull st2 = pack2(stp, stp);

        float4* o = (float4*)(obase) + lane;
        if (cbase + WCHUNK <= L) {
#pragma unroll
            for (int j = 0; j < JF; j++) {
                float4 v;
                unpack2(pa, v.x, v.y);
                unpack2(pb, v.z, v.w);
                o[j * 32] = v;                   // unconditional STG.128
                pa = mul2(pa, st2);
                pb = mul2(pb, st2);
            }
        } else {
            const int lrem = cbase + 4 * lane;
#pragma unroll
            for (int j = 0; j < JF; j++) {
                float4 v;
                unpack2(pa, v.x, v.y);
                unpack2(pb, v.z, v.w);
                if (lrem + j * 128 + 3 < L) o[j * 32] = v;
                pa = mul2(pa, st2);
                pb = mul2(pb, st2);
            }
        }
    } else {
        // ---- cold path: direct evaluation from smem coefficients ----
        for (int k = 0; k < WCHUNK / 32; k++) {
            const int l = cbase + lane + k * 32;
            float lf = (float)l;
            float acc = 0.0f;
#pragma unroll
            for (int i = 0; i < NH; i++)
                acc += s_c[i] * ex2(s_dtA[i] * LOG2E * lf);   // broadcast LDS
            if (l < L) obase[lane + k * 32] = acc;
        }
    }
}

extern "C" void kernel_launch(void* const* d_in, const int* in_sizes, int n_in,
                              void* d_out, int out_size)
{
    const float* log_dt     = (const float*)d_in[0];
    const float* C          = (const float*)d_in[1];
    const float* log_A_real = (const float*)d_in[2];
    const float* A_imag     = (const float*)d_in[3];
    float* out = (float*)d_out;

    const int H = in_sizes[0];
    const int L = out_size / H;

    const int chunks = (L + WCHUNK - 1) / WCHUNK;       // warps per head
    dim3 grid((chunks + WPB - 1) / WPB, H);
    s4d_kernel<<<grid, TPB>>>(log_dt, C, log_A_real, A_imag, out, L);
}

// round 10
// speedup vs baseline: 1.0037x; 1.0037x over previous
#include <cuda_runtime.h>
#include <cstdint>

// S4D Vandermonde kernel:  K[h,l] = 2 * sum_n C_eff[h,n] * exp(dtA[h,n] * l)
// H=256, NH=N/2=32, L=16384.
//
// With this problem's init dtA[h,n] is constant across n, so
// K[h,l] = S[h] * exp(dtA[h]*l): one geometric recurrence per head.
// R10 = R9 (block-level setup: warp 0 alone runs the LDG -> coeff -> ballot
// -> shfl-reduce prologue, publishes {S,E,q1,stp,flag} + per-n c/dtA via
// smem, one barrier) with the R9 register blowup fixed: __launch_bounds__
// (256, 8) pins ptxas to the 32-reg budget the hot path needs (R9 went to
// 80 regs from the unrolled cold path -> occ 31% -> regression), and the
// cold path is only partially unrolled. Hot loop unchanged from R8:
// seed = S*exp(E*lb), then STG.128 + 2 mul.f32x2 per j-step.

#define TPB    256
#define NH     32
#define WPB    (TPB / 32)      // warps per block
#define JF     4               // float4 stores per lane
#define WCHUNK (32 * 4 * JF)   // 512 l-elements per warp
#define LOG2E  1.4426950408889634f

typedef unsigned long long ull;

__device__ __forceinline__ float ex2(float x) {
    float y; asm("ex2.approx.f32 %0, %1;" : "=f"(y) : "f"(x));
    return y;
}
__device__ __forceinline__ ull mul2(ull a, ull b) {
    ull d; asm("mul.rn.f32x2 %0, %1, %2;" : "=l"(d) : "l"(a), "l"(b));
    return d;
}
__device__ __forceinline__ ull pack2(float lo, float hi) {
    ull u; asm("mov.b64 %0, {%1, %2};" : "=l"(u) : "f"(lo), "f"(hi));
    return u;
}
__device__ __forceinline__ void unpack2(ull u, float& lo, float& hi) {
    asm("mov.b64 {%0, %1}, %2;" : "=f"(lo), "=f"(hi) : "l"(u));
}

__global__ void __launch_bounds__(TPB, 8) s4d_kernel(
    const float* __restrict__ log_dt,      // [H]
    const float* __restrict__ C,           // [H, NH]
    const float* __restrict__ log_A_real,  // [H, NH]
    const float* __restrict__ A_imag,      // [H, NH]
    float* __restrict__ out,               // [H, L]
    int L)
{
    __shared__ float s_c[NH];              // cold path
    __shared__ float s_dtA[NH];            // cold path
    __shared__ float s_S, s_E, s_q1, s_stp;
    __shared__ int   s_flag;

    const int h    = blockIdx.y;
    const int t    = threadIdx.x;
    const int lane = t & 31;

    if (t < 32) {   // setup warp: lane == n. Mirrors reference fp32 math with
                    // MUFU-grade exp/div (rel err ~2^-21 vs the 1e-3 gate).
        float dt     = ex2(log_dt[h] * LOG2E);
        float Ar     = -ex2(log_A_real[h * NH + lane] * LOG2E);
        float Ai     = A_imag[h * NH + lane];
        float dtA    = Ar * dt;
        float den    = Ar * Ar + Ai * Ai;
        float expdtA = ex2(dtA * LOG2E);
        float c = __fdividef(2.0f * C[h * NH + lane] * (expdtA - 1.0f) * Ar, den);

        s_c[lane]   = c;
        s_dtA[lane] = dtA;

        const float dtA0  = __shfl_sync(0xffffffffu, dtA, 0);
        const unsigned eq = __ballot_sync(0xffffffffu,
                              __float_as_uint(dtA) == __float_as_uint(dtA0));
        float S = c;
#pragma unroll
        for (int o = 16; o; o >>= 1)
            S += __shfl_xor_sync(0xffffffffu, S, o);

        if (lane == 0) {
            float E = dtA0 * LOG2E;
            s_S    = S;
            s_E    = E;
            s_q1   = expdtA;              // lane0's exp(dtA) == exp(dtA0)
            s_stp  = ex2(E * 128.0f);     // j-step ratio (32 lanes * 4)
            s_flag = (eq == 0xffffffffu);
        }
    }
    __syncthreads();

    const int cbase = (blockIdx.x * WPB + (t >> 5)) * WCHUNK;
    if (cbase >= L) return;
    float* obase = out + (size_t)h * L + cbase;

    if (s_flag) {
        // ---- hot path: K = S * exp(dtA0 * l); S folded into the seed ----
        const float S   = s_S;
        const float E   = s_E;
        const float q1  = s_q1;
        const float stp = s_stp;

        float p0 = S * ex2(E * (float)(cbase + 4 * lane));   // one MUFU/thread
        float p1 = p0 * q1;
        float p2 = p1 * q1;
        float p3 = p2 * q1;

        ull pa = pack2(p0, p1);
        ull pb = pack2(p2, p3);
        const ull st2 = pack2(stp, stp);

        float4* o = (float4*)(obase) + lane;
        if (cbase + WCHUNK <= L) {
#pragma unroll
            for (int j = 0; j < JF; j++) {
                float4 v;
                unpack2(pa, v.x, v.y);
                unpack2(pb, v.z, v.w);
                o[j * 32] = v;                   // unconditional STG.128
                pa = mul2(pa, st2);
                pb = mul2(pb, st2);
            }
        } else {
            const int lrem = cbase + 4 * lane;
#pragma unroll
            for (int j = 0; j < JF; j++) {
                float4 v;
                unpack2(pa, v.x, v.y);
                unpack2(pb, v.z, v.w);
                if (lrem + j * 128 + 3 < L) o[j * 32] = v;
                pa = mul2(pa, st2);
                pb = mul2(pb, st2);
            }
        }
    } else {
        // ---- cold path: direct evaluation from smem coefficients ----
        // Partially unrolled so it can't inflate the register allocation.
        for (int k = 0; k < WCHUNK / 32; k++) {
            const int l = cbase + lane + k * 32;
            float lf = (float)l;
            float acc = 0.0f;
#pragma unroll 4
            for (int i = 0; i < NH; i++)
                acc += s_c[i] * ex2(s_dtA[i] * LOG2E * lf);   // broadcast LDS
            if (l < L) obase[lane + k * 32] = acc;
        }
    }
}

extern "C" void kernel_launch(void* const* d_in, const int* in_sizes, int n_in,
                              void* d_out, int out_size)
{
    const float* log_dt     = (const float*)d_in[0];
    const float* C          = (const float*)d_in[1];
    const float* log_A_real = (const float*)d_in[2];
    const float* A_imag     = (const float*)d_in[3];
    float* out = (float*)d_out;

    const int H = in_sizes[0];
    const int L = out_size / H;

    const int chunks = (L + WCHUNK - 1) / WCHUNK;       // warps per head
    dim3 grid((chunks + WPB - 1) / WPB, H);
    s4d_kernel<<<grid, TPB>>>(log_dt, C, log_A_real, A_imag, out, L);
}